// round 2
// baseline (speedup 1.0000x reference)
#include <cuda_runtime.h>
#include <math.h>

#define IN_DIM 512
#define HID    1024
#define MEMD   1024
#define OUTD   512
#define BATCH  4096

// ---------------- device scratch (static, no allocation) ----------------
__device__ __align__(16) float g_out_v[OUTD];
__device__ __align__(16) float g_mem_v[MEMD];
__device__ __align__(16) float g_prod_v[HID];
__device__ __align__(16) float g_rgmem_v[MEMD];
__device__ __align__(16) float g_wg_v[MEMD];
__device__ __align__(16) float g_hid_v[HID];
__device__ __align__(16) float g_c_inp[HID];
__device__ __align__(16) float g_c_ig[HID];
__device__ __align__(16) float g_c_rg[MEMD];

__device__ __align__(16) float g_pre[3u * HID * BATCH];        // 48 MB
__device__ __align__(16) float g_rgmem_b[(size_t)MEMD * BATCH]; // 16 MB
__device__ __align__(16) float g_hidden_b[(size_t)HID * BATCH]; // 16 MB

struct P {
    const float *input;
    const float *W_ig, *b_ig, *W_rig, *b_rig, *W_mig, *b_mig;
    const float *W_inp, *b_inp, *W_rinp, *b_rinp;
    const float *W_rg, *b_rg, *W_rrg, *b_rrg, *W_mrg, *b_mrg;
    const float *W_dec, *b_dec;
    const float *W_wg, *b_wg, *W_rwg, *b_rwg, *W_mwg, *b_mwg;
    const float *W_enc, *b_enc, *w_ho;
};

__device__ __forceinline__ float sigf(float x) { return 1.0f / (1.0f + expf(-x)); }

__device__ __forceinline__ float warp_sum(float v) {
    #pragma unroll
    for (int o = 16; o; o >>= 1) v += __shfl_xor_sync(0xFFFFFFFFu, v, o);
    return v;
}

// ---------------- init: zero state ----------------
__global__ void k_init() {
    int i = blockIdx.x * blockDim.x + threadIdx.x;
    if (i < OUTD) g_out_v[i] = 0.0f;
    else if (i < OUTD + MEMD) g_mem_v[i - OUTD] = 0.0f;
}

// ---------------- vector step: gates (MODE 0: steps 0-3, MODE 1: step-4 constants) ----------------
template <int MODE>
__global__ void k_vec_gates(P p) {
    int warp = (blockIdx.x * blockDim.x + threadIdx.x) >> 5;
    int lane = threadIdx.x & 31;
    if (warp >= HID) return;
    int h = warp;
    float s_bi = 0.f, s_ig = 0.f, s_rg = 0.f, s_wg = 0.f;
    for (int k = lane; k < OUTD; k += 32) {
        float ov = g_out_v[k];
        s_bi += ov * p.W_rinp[h * OUTD + k];
        s_ig += ov * p.W_rig[h * OUTD + k];
        s_rg += ov * p.W_rrg[h * OUTD + k];
        if (MODE == 0) s_wg += ov * p.W_rwg[h * OUTD + k];
    }
    for (int k = lane; k < MEMD; k += 32) {
        float mv = g_mem_v[k];
        s_ig += mv * p.W_mig[h * MEMD + k];
        s_rg += mv * p.W_mrg[h * MEMD + k];
        if (MODE == 0) s_wg += mv * p.W_mwg[h * MEMD + k];
    }
    s_bi = warp_sum(s_bi);
    s_ig = warp_sum(s_ig);
    s_rg = warp_sum(s_rg);
    if (MODE == 0) s_wg = warp_sum(s_wg);
    if (lane == 0) {
        float pbi = s_bi + p.b_inp[h] + p.b_rinp[h];
        float pig = s_ig + p.b_ig[h] + p.b_mig[h] + p.b_rig[h];
        float prg = s_rg + p.b_rg[h] + p.b_mrg[h] + p.b_rrg[h];
        if (MODE == 0) {
            float pwg = s_wg + p.b_wg[h] + p.b_mwg[h] + p.b_rwg[h];
            g_prod_v[h]  = sigf(pbi) * sigf(pig);
            g_rgmem_v[h] = sigf(prg) * g_mem_v[h];
            g_wg_v[h]    = sigf(pwg);
        } else {
            g_c_inp[h] = pbi;
            g_c_ig[h]  = pig;
            g_c_rg[h]  = prg;
        }
    }
}

// ---------------- vector step: hidden = decoder(rg*mem) + b + prod ----------------
__global__ void k_vec_hidden(P p) {
    int warp = (blockIdx.x * blockDim.x + threadIdx.x) >> 5;
    int lane = threadIdx.x & 31;
    if (warp >= HID) return;
    int h = warp;
    float s = 0.f;
    for (int k = lane; k < MEMD; k += 32) s += g_rgmem_v[k] * p.W_dec[h * MEMD + k];
    s = warp_sum(s);
    if (lane == 0) g_hid_v[h] = s + p.b_dec[h] + g_prod_v[h];
}

// ---------------- vector step: mem update (encoder/tanh) + out = hidden @ w_ho.T ----------------
__global__ void k_vec_update(P p) {
    int warp = (blockIdx.x * blockDim.x + threadIdx.x) >> 5;
    int lane = threadIdx.x & 31;
    if (warp >= MEMD + OUTD) return;
    if (warp < MEMD) {
        int m = warp;
        float s = 0.f;
        for (int k = lane; k < HID; k += 32) s += g_hid_v[k] * p.W_enc[m * HID + k];
        s = warp_sum(s);
        if (lane == 0) {
            float e = tanhf(s + p.b_enc[m]);
            float w = g_wg_v[m];
            g_mem_v[m] = (1.0f - w) * g_mem_v[m] + w * e;
        }
    } else {
        int o = warp - MEMD;
        float s = 0.f;
        for (int k = lane; k < HID; k += 32) s += g_hid_v[k] * p.w_ho[o * HID + k];
        s = warp_sum(s);
        if (lane == 0) g_out_v[o] = s;
    }
}

// ---------------- SGEMM: C[M,N] = A[M,K] @ B[K,N] (row-major), 128x128x8, 8x8 microtile ----------------
// MODE 0: plain store      MODE 1: C = acc + bias[m] + addm[m,n]      MODE 2: C[n*OUTD + m] = acc
template <int MODE>
__global__ __launch_bounds__(256) void k_sgemm(const float* __restrict__ A,
                                               const float* __restrict__ B,
                                               float* __restrict__ C,
                                               int M, int N, int K,
                                               const float* __restrict__ bias,
                                               const float* __restrict__ addm) {
    __shared__ float As[8][128];
    __shared__ float Bs[8][128];
    const int tid = threadIdx.x;
    const int m0 = blockIdx.y * 128, n0 = blockIdx.x * 128;

    const int a_row = tid >> 1;          // 0..127
    const int a_col = (tid & 1) * 4;     // 0 or 4
    const int b_row = tid >> 5;          // 0..7
    const int b_col = (tid & 31) * 4;    // 0..124

    const int tx = tid & 15, ty = tid >> 4;

    float acc[8][8];
    #pragma unroll
    for (int i = 0; i < 8; i++)
        #pragma unroll
        for (int j = 0; j < 8; j++) acc[i][j] = 0.f;

    const float* Ap = A + (size_t)(m0 + a_row) * K + a_col;
    const float* Bp = B + (size_t)b_row * N + n0 + b_col;

    for (int k0 = 0; k0 < K; k0 += 8) {
        float4 av = *(const float4*)(Ap + k0);
        As[a_col + 0][a_row] = av.x;
        As[a_col + 1][a_row] = av.y;
        As[a_col + 2][a_row] = av.z;
        As[a_col + 3][a_row] = av.w;
        *(float4*)&Bs[b_row][b_col] = *(const float4*)(Bp + (size_t)k0 * N);
        __syncthreads();
        #pragma unroll
        for (int k = 0; k < 8; k++) {
            float4 a0 = *(const float4*)&As[k][ty * 4];
            float4 a1 = *(const float4*)&As[k][64 + ty * 4];
            float4 b0 = *(const float4*)&Bs[k][tx * 4];
            float4 b1 = *(const float4*)&Bs[k][64 + tx * 4];
            float ar[8] = {a0.x, a0.y, a0.z, a0.w, a1.x, a1.y, a1.z, a1.w};
            float br[8] = {b0.x, b0.y, b0.z, b0.w, b1.x, b1.y, b1.z, b1.w};
            #pragma unroll
            for (int i = 0; i < 8; i++)
                #pragma unroll
                for (int j = 0; j < 8; j++) acc[i][j] = fmaf(ar[i], br[j], acc[i][j]);
        }
        __syncthreads();
    }

    #pragma unroll
    for (int i = 0; i < 8; i++) {
        int m = m0 + ((i < 4) ? (ty * 4 + i) : (64 + ty * 4 + i - 4));
        float bv = (MODE == 1) ? bias[m] : 0.f;
        #pragma unroll
        for (int j = 0; j < 8; j++) {
            int n = n0 + ((j < 4) ? (tx * 4 + j) : (64 + tx * 4 + j - 4));
            float v = acc[i][j];
            if (MODE == 1) v += bv + addm[(size_t)m * N + n];
            if (MODE == 2) C[(size_t)n * OUTD + m] = v;
            else           C[(size_t)m * N + n] = v;
        }
    }
}

// ---------------- fused gate elementwise (step 4) ----------------
// prod[h,b] = sig(pre_inp + c_inp[h]) * sig(pre_ig + c_ig[h])  (overwrites pre rows 0..1023)
// rgmem[h,b] = sig(pre_rg + c_rg[h]) * mem_v[h]
__global__ void k_gate_elem(float* __restrict__ pre, float* __restrict__ rgb) {
    size_t idx = ((size_t)blockIdx.x * blockDim.x + threadIdx.x) * 4;
    int h = (int)(idx >> 12);  // /4096, constant over the float4
    float ci = g_c_inp[h], cg = g_c_ig[h], cr = g_c_rg[h], mv = g_mem_v[h];
    float4 pi = *(float4*)(pre + idx);
    float4 pg = *(float4*)(pre + (size_t)HID * BATCH + idx);
    float4 pr = *(float4*)(pre + (size_t)2 * HID * BATCH + idx);
    float4 o1, o2;
    o1.x = sigf(pi.x + ci) * sigf(pg.x + cg);
    o1.y = sigf(pi.y + ci) * sigf(pg.y + cg);
    o1.z = sigf(pi.z + ci) * sigf(pg.z + cg);
    o1.w = sigf(pi.w + ci) * sigf(pg.w + cg);
    o2.x = sigf(pr.x + cr) * mv;
    o2.y = sigf(pr.y + cr) * mv;
    o2.z = sigf(pr.z + cr) * mv;
    o2.w = sigf(pr.w + cr) * mv;
    *(float4*)(pre + idx) = o1;
    *(float4*)(rgb + idx) = o2;
}

// ---------------- launch ----------------
extern "C" void kernel_launch(void* const* d_in, const int* in_sizes, int n_in,
                              void* d_out, int out_size) {
    P p;
    const float** f = (const float**)&p;
    for (int i = 0; i < 28; i++) f[i] = (const float*)d_in[i];
    // order: input, (W,b) x {inpgate, rec_inpgate, mem_inpgate, inp, rec_inp,
    //         readgate, rec_readgate, mem_readgate, decoder, writegate,
    //         rec_writegate, mem_writegate, encoder}, w_hid_out
    // struct P is declared in exactly this order.

    float *pre, *rgb, *hidb;
    cudaGetSymbolAddress((void**)&pre, g_pre);
    cudaGetSymbolAddress((void**)&rgb, g_rgmem_b);
    cudaGetSymbolAddress((void**)&hidb, g_hidden_b);

    k_init<<<6, 256>>>();

    // steps 0..3: batch-uniform vector recurrence
    for (int s = 0; s < 4; s++) {
        k_vec_gates<0><<<128, 256>>>(p);
        k_vec_hidden<<<128, 256>>>(p);
        k_vec_update<<<192, 256>>>(p);
    }

    // step-4 batch-uniform constants (pre-activation offsets)
    k_vec_gates<1><<<128, 256>>>(p);

    // step 4 batched: 3 input GEMMs
    dim3 g1(BATCH / 128, HID / 128);  // (32, 8)
    k_sgemm<0><<<g1, 256>>>(p.W_inp, p.input, pre,                        HID, BATCH, IN_DIM, nullptr, nullptr);
    k_sgemm<0><<<g1, 256>>>(p.W_ig,  p.input, pre + (size_t)HID * BATCH,  HID, BATCH, IN_DIM, nullptr, nullptr);
    k_sgemm<0><<<g1, 256>>>(p.W_rg,  p.input, pre + (size_t)2*HID*BATCH,  HID, BATCH, IN_DIM, nullptr, nullptr);

    // fused sigmoid gates
    k_gate_elem<<<(HID * BATCH) / (256 * 4), 256>>>(pre, rgb);

    // decoder GEMM, epilogue adds b_dec + block_inp*inp_gate -> hidden
    k_sgemm<1><<<g1, 256>>>(p.W_dec, rgb, hidb, MEMD, BATCH, MEMD, p.b_dec, pre);

    // hid_out GEMM, transposed store straight into d_out[b*512 + o]
    dim3 g3(BATCH / 128, OUTD / 128);  // (32, 4)
    k_sgemm<2><<<g3, 256>>>(p.w_ho, hidb, (float*)d_out, OUTD, BATCH, HID, nullptr, nullptr);
}

// round 4
// speedup vs baseline: 2.5229x; 2.5229x over previous
#include <cuda_runtime.h>
#include <math.h>
#include <stdint.h>

#define IN_DIM 512
#define HID    1024
#define MEMD   1024
#define OUTD   512
#define BATCH  4096

#define TM 128
#define TN 128
#define KC 32
#define GEMM_THREADS 256
#define SA 36                       // padded smem stride (floats)
#define CH_SZ (128 * SA)            // one chunk buffer (floats)
#define SMEM_FLOATS (4 * CH_SZ)     // A0 A1 B0 B1
#define SMEM_BYTES (SMEM_FLOATS * 4)

// ---------------- device scratch ----------------
__device__ __align__(16) float g_xT [(size_t)BATCH * IN_DIM];   // input^T [B, K]
__device__ __align__(16) float g_pre[3][(size_t)BATCH * HID];   // pre-activations [B, H]
__device__ __align__(16) float g_rgm[(size_t)BATCH * MEMD];
__device__ __align__(16) float g_hid[(size_t)BATCH * HID];

__device__ __align__(16) float g_out_v[OUTD];
__device__ __align__(16) float g_mem_v[MEMD];
__device__ __align__(16) float g_prod_v[HID];
__device__ __align__(16) float g_rgmem_v[MEMD];
__device__ __align__(16) float g_wg_v[MEMD];
__device__ __align__(16) float g_hid_v[HID];
__device__ __align__(16) float g_c_inp[HID];
__device__ __align__(16) float g_c_ig[HID];
__device__ __align__(16) float g_c_rg[MEMD];

struct P {
    const float *input;
    const float *W_ig, *b_ig, *W_rig, *b_rig, *W_mig, *b_mig;
    const float *W_inp, *b_inp, *W_rinp, *b_rinp;
    const float *W_rg, *b_rg, *W_rrg, *b_rrg, *W_mrg, *b_mrg;
    const float *W_dec, *b_dec;
    const float *W_wg, *b_wg, *W_rwg, *b_rwg, *W_mwg, *b_mwg;
    const float *W_enc, *b_enc, *w_ho;
};

__device__ __forceinline__ float sigf(float x) { return 1.0f / (1.0f + expf(-x)); }
__device__ __forceinline__ float warp_sum(float v) {
    #pragma unroll
    for (int o = 16; o; o >>= 1) v += __shfl_xor_sync(0xFFFFFFFFu, v, o);
    return v;
}
__device__ __forceinline__ float dot4(float4 a, float4 b) {
    return a.x * b.x + a.y * b.y + a.z * b.z + a.w * b.w;
}
__device__ __forceinline__ uint32_t f2tf32(float f) {
    uint32_t r;
    asm("cvt.rna.tf32.f32 %0, %1;" : "=r"(r) : "f"(f));
    return r;
}
__device__ __forceinline__ void mma1688(float* c, const uint32_t* a, const uint32_t* b) {
    asm volatile(
        "mma.sync.aligned.m16n8k8.row.col.f32.tf32.tf32.f32 "
        "{%0,%1,%2,%3}, {%4,%5,%6,%7}, {%8,%9}, {%0,%1,%2,%3};"
        : "+f"(c[0]), "+f"(c[1]), "+f"(c[2]), "+f"(c[3])
        : "r"(a[0]), "r"(a[1]), "r"(a[2]), "r"(a[3]), "r"(b[0]), "r"(b[1]));
}

// ---------------- init ----------------
__global__ void k_init() {
    int i = blockIdx.x * blockDim.x + threadIdx.x;
    if (i < OUTD) g_out_v[i] = 0.0f;
    else if (i < OUTD + MEMD) g_mem_v[i - OUTD] = 0.0f;
}

// ---------------- transpose input [512,4096] -> g_xT [4096,512] ----------------
__global__ void k_transpose(const float* __restrict__ in) {
    __shared__ float t[32][33];
    int bx = blockIdx.x * 32;
    int by = blockIdx.y * 32;
    for (int j = threadIdx.y; j < 32; j += 8)
        t[j][threadIdx.x] = in[(size_t)(by + j) * BATCH + bx + threadIdx.x];
    __syncthreads();
    for (int j = threadIdx.y; j < 32; j += 8)
        g_xT[(size_t)(bx + j) * IN_DIM + by + threadIdx.x] = t[threadIdx.x][j];
}

// ---------------- block reduce helper (4 warps, 128 threads) ----------------
__device__ __forceinline__ void blk_red4(float* s, float v0, float v1, float v2, float v3,
                                         int wid, int lane, float* out) {
    v0 = warp_sum(v0); v1 = warp_sum(v1); v2 = warp_sum(v2); v3 = warp_sum(v3);
    if (lane == 0) { s[wid*4+0]=v0; s[wid*4+1]=v1; s[wid*4+2]=v2; s[wid*4+3]=v3; }
    __syncthreads();
    if (threadIdx.x == 0) {
        #pragma unroll
        for (int i = 0; i < 4; i++)
            out[i] = s[0*4+i] + s[1*4+i] + s[2*4+i] + s[3*4+i];
    }
}

// ---------------- vector steps: block-per-row, 128 threads ----------------
template <int MODE>
__global__ void k_vec_gates(P p) {
    __shared__ float red[16];
    const int h = blockIdx.x;
    const int t = threadIdx.x, wid = t >> 5, lane = t & 31;
    const float4* ov = (const float4*)g_out_v;   // 128 float4
    const float4* mv = (const float4*)g_mem_v;   // 256 float4
    float s_bi = 0.f, s_ig = 0.f, s_rg = 0.f, s_wg = 0.f;
    {
        float4 o = ov[t];
        s_bi = dot4(o, ((const float4*)(p.W_rinp + (size_t)h * OUTD))[t]);
        s_ig = dot4(o, ((const float4*)(p.W_rig  + (size_t)h * OUTD))[t]);
        s_rg = dot4(o, ((const float4*)(p.W_rrg  + (size_t)h * OUTD))[t]);
        if (MODE == 0) s_wg = dot4(o, ((const float4*)(p.W_rwg + (size_t)h * OUTD))[t]);
    }
    #pragma unroll
    for (int j = 0; j < 2; j++) {
        int k = t + j * 128;
        float4 m = mv[k];
        s_ig += dot4(m, ((const float4*)(p.W_mig + (size_t)h * MEMD))[k]);
        s_rg += dot4(m, ((const float4*)(p.W_mrg + (size_t)h * MEMD))[k]);
        if (MODE == 0) s_wg += dot4(m, ((const float4*)(p.W_mwg + (size_t)h * MEMD))[k]);
    }
    float out[4];
    blk_red4(red, s_bi, s_ig, s_rg, s_wg, wid, lane, out);
    if (threadIdx.x == 0) {
        float pbi = out[0] + p.b_inp[h] + p.b_rinp[h];
        float pig = out[1] + p.b_ig[h] + p.b_mig[h] + p.b_rig[h];
        float prg = out[2] + p.b_rg[h] + p.b_mrg[h] + p.b_rrg[h];
        if (MODE == 0) {
            float pwg = out[3] + p.b_wg[h] + p.b_mwg[h] + p.b_rwg[h];
            g_prod_v[h]  = sigf(pbi) * sigf(pig);
            g_rgmem_v[h] = sigf(prg) * g_mem_v[h];
            g_wg_v[h]    = sigf(pwg);
        } else {
            g_c_inp[h] = pbi;
            g_c_ig[h]  = pig;
            g_c_rg[h]  = prg;
        }
    }
}

__global__ void k_vec_hidden(P p) {
    __shared__ float red[4];
    const int h = blockIdx.x;
    const int t = threadIdx.x, wid = t >> 5, lane = t & 31;
    const float4* rg = (const float4*)g_rgmem_v;
    const float4* Wd = (const float4*)(p.W_dec + (size_t)h * MEMD);
    float s = dot4(rg[t], Wd[t]) + dot4(rg[t + 128], Wd[t + 128]);
    s = warp_sum(s);
    if (lane == 0) red[wid] = s;
    __syncthreads();
    if (t == 0)
        g_hid_v[h] = red[0] + red[1] + red[2] + red[3] + p.b_dec[h] + g_prod_v[h];
}

__global__ void k_vec_update(P p) {
    __shared__ float red[4];
    const int r = blockIdx.x;
    const int t = threadIdx.x, wid = t >> 5, lane = t & 31;
    const float4* hv = (const float4*)g_hid_v;
    const float4* W = (r < MEMD) ? (const float4*)(p.W_enc + (size_t)r * HID)
                                 : (const float4*)(p.w_ho + (size_t)(r - MEMD) * HID);
    float s = dot4(hv[t], W[t]) + dot4(hv[t + 128], W[t + 128]);
    s = warp_sum(s);
    if (lane == 0) red[wid] = s;
    __syncthreads();
    if (t == 0) {
        s = red[0] + red[1] + red[2] + red[3];
        if (r < MEMD) {
            float e = tanhf(s + p.b_enc[r]);
            float w = g_wg_v[r];
            g_mem_v[r] = (1.0f - w) * g_mem_v[r] + w * e;
        } else {
            g_out_v[r - MEMD] = s;
        }
    }
}

// ---------------- tf32 mma.sync GEMM: C[M,N] = A[M,K] @ B[N,K]^T ----------------
// A: [B, K] row-major, B: [N_feat, K] row-major.
// MODE 0: C[m*ldC+n] = acc     MODE 1: C[m*ldC+n] = acc + bias[n] + addm[m*ldC+n]
template <int MODE>
__global__ __launch_bounds__(GEMM_THREADS, 1) void k_tgemm(
    const float* __restrict__ A, const float* __restrict__ B, float* __restrict__ C,
    int K, int ldC, const float* __restrict__ bias, const float* __restrict__ addm)
{
    extern __shared__ float smem[];
    const int tid = threadIdx.x, wid = tid >> 5, lane = tid & 31;
    const int m0 = blockIdx.y * TM, n0 = blockIdx.x * TN;
    const int g = lane >> 2, t4 = lane & 3;
    const int wm = (wid >> 2) * 64, wn = (wid & 3) * 32;

    const int row = tid >> 3;        // 0..31 per j-step? no: see loader
    const int nc = K / KC;

    float acc[4][4][4];
    #pragma unroll
    for (int i = 0; i < 4; i++)
        #pragma unroll
        for (int j = 0; j < 4; j++)
            #pragma unroll
            for (int q = 0; q < 4; q++) acc[i][j][q] = 0.f;

    float4 pa[4], pb[4];

    auto ldg_chunk = [&](int k0) {
        #pragma unroll
        for (int j = 0; j < 4; j++) {
            int s = j * GEMM_THREADS + tid;       // 0..1023
            int r = s >> 3, kq = s & 7;
            pa[j] = *(const float4*)(A + (size_t)(m0 + r) * K + k0 + kq * 4);
            pb[j] = *(const float4*)(B + (size_t)(n0 + r) * K + k0 + kq * 4);
        }
    };
    auto sts_chunk = [&](int buf) {
        float* as_ = smem + buf * CH_SZ;
        float* bs_ = smem + 2 * CH_SZ + buf * CH_SZ;
        #pragma unroll
        for (int j = 0; j < 4; j++) {
            int s = j * GEMM_THREADS + tid;
            int r = s >> 3, kq = s & 7;
            uint32_t* ap = (uint32_t*)(as_ + r * SA + kq * 4);
            uint32_t* bp = (uint32_t*)(bs_ + r * SA + kq * 4);
            ap[0] = f2tf32(pa[j].x); ap[1] = f2tf32(pa[j].y);
            ap[2] = f2tf32(pa[j].z); ap[3] = f2tf32(pa[j].w);
            bp[0] = f2tf32(pb[j].x); bp[1] = f2tf32(pb[j].y);
            bp[2] = f2tf32(pb[j].z); bp[3] = f2tf32(pb[j].w);
        }
    };
    auto compute = [&](int buf) {
        const uint32_t* as_ = (const uint32_t*)(smem + buf * CH_SZ);
        const uint32_t* bs_ = (const uint32_t*)(smem + 2 * CH_SZ + buf * CH_SZ);
        #pragma unroll
        for (int ks = 0; ks < 4; ks++) {
            const int kb = ks * 8;
            uint32_t af[4][4], bf[4][2];
            #pragma unroll
            for (int mt = 0; mt < 4; mt++) {
                int m = wm + mt * 16 + g;
                af[mt][0] = as_[m * SA + kb + t4];
                af[mt][1] = as_[(m + 8) * SA + kb + t4];
                af[mt][2] = as_[m * SA + kb + t4 + 4];
                af[mt][3] = as_[(m + 8) * SA + kb + t4 + 4];
            }
            #pragma unroll
            for (int nt = 0; nt < 4; nt++) {
                int n = wn + nt * 8 + g;
                bf[nt][0] = bs_[n * SA + kb + t4];
                bf[nt][1] = bs_[n * SA + kb + t4 + 4];
            }
            #pragma unroll
            for (int mt = 0; mt < 4; mt++)
                #pragma unroll
                for (int nt = 0; nt < 4; nt++)
                    mma1688(acc[mt][nt], af[mt], bf[nt]);
        }
    };

    ldg_chunk(0);
    sts_chunk(0);
    __syncthreads();
    for (int c = 0; c < nc; c++) {
        if (c + 1 < nc) ldg_chunk((c + 1) * KC);
        compute(c & 1);
        if (c + 1 < nc) sts_chunk((c + 1) & 1);
        __syncthreads();
    }

    // ---- epilogue: stage to smem (stride 132), then coalesced float4 stores ----
    float* stg = smem;
    #pragma unroll
    for (int mt = 0; mt < 4; mt++) {
        #pragma unroll
        for (int nt = 0; nt < 4; nt++) {
            int rr = wm + mt * 16 + g;
            int cc = wn + nt * 8 + t4 * 2;
            *(float2*)(stg + rr * 132 + cc)       = make_float2(acc[mt][nt][0], acc[mt][nt][1]);
            *(float2*)(stg + (rr + 8) * 132 + cc) = make_float2(acc[mt][nt][2], acc[mt][nt][3]);
        }
    }
    __syncthreads();
    #pragma unroll
    for (int j = 0; j < 16; j++) {
        int s = j * GEMM_THREADS + tid;     // 0..4095
        int r = s >> 5, cq = s & 31;        // 128 rows x 32 float4
        int m = m0 + r, n = n0 + cq * 4;
        float4 v = *(float4*)(stg + r * 132 + cq * 4);
        if (MODE == 1) {
            const float4 bv = *(const float4*)(bias + n);
            const float4 av = *(const float4*)(addm + (size_t)m * ldC + n);
            v.x += bv.x + av.x; v.y += bv.y + av.y;
            v.z += bv.z + av.z; v.w += bv.w + av.w;
        }
        *(float4*)(C + (size_t)m * ldC + n) = v;
    }
}

// ---------------- fused gate elementwise (step 4), [B, F] layout ----------------
__global__ void k_gate_elem() {
    size_t idx = ((size_t)blockIdx.x * blockDim.x + threadIdx.x) * 4;
    int h = (int)(idx & (HID - 1));
    float4 ci = *(const float4*)&g_c_inp[h];
    float4 cg = *(const float4*)&g_c_ig[h];
    float4 cr = *(const float4*)&g_c_rg[h];
    float4 mv = *(const float4*)&g_mem_v[h];
    float4 pi = *(const float4*)&g_pre[0][idx];
    float4 pg = *(const float4*)&g_pre[1][idx];
    float4 pr = *(const float4*)&g_pre[2][idx];
    float4 o1, o2;
    o1.x = sigf(pi.x + ci.x) * sigf(pg.x + cg.x);
    o1.y = sigf(pi.y + ci.y) * sigf(pg.y + cg.y);
    o1.z = sigf(pi.z + ci.z) * sigf(pg.z + cg.z);
    o1.w = sigf(pi.w + ci.w) * sigf(pg.w + cg.w);
    o2.x = sigf(pr.x + cr.x) * mv.x;
    o2.y = sigf(pr.y + cr.y) * mv.y;
    o2.z = sigf(pr.z + cr.z) * mv.z;
    o2.w = sigf(pr.w + cr.w) * mv.w;
    *(float4*)&g_pre[0][idx] = o1;
    *(float4*)&g_rgm[idx]    = o2;
}

// ---------------- launch ----------------
extern "C" void kernel_launch(void* const* d_in, const int* in_sizes, int n_in,
                              void* d_out, int out_size) {
    P p;
    const float** f = (const float**)&p;
    for (int i = 0; i < 28; i++) f[i] = (const float*)d_in[i];

    float *xT, *pre, *rgm, *hid;
    cudaGetSymbolAddress((void**)&xT,  g_xT);
    cudaGetSymbolAddress((void**)&pre, g_pre);
    cudaGetSymbolAddress((void**)&rgm, g_rgm);
    cudaGetSymbolAddress((void**)&hid, g_hid);
    float* pre0 = pre;
    float* pre1 = pre + (size_t)BATCH * HID;
    float* pre2 = pre + (size_t)2 * BATCH * HID;

    cudaFuncSetAttribute(k_tgemm<0>, cudaFuncAttributeMaxDynamicSharedMemorySize, SMEM_BYTES);
    cudaFuncSetAttribute(k_tgemm<1>, cudaFuncAttributeMaxDynamicSharedMemorySize, SMEM_BYTES);

    k_init<<<6, 256>>>();
    k_transpose<<<dim3(BATCH / 32, IN_DIM / 32), dim3(32, 8)>>>(p.input);

    for (int s = 0; s < 4; s++) {
        k_vec_gates<0><<<HID, 128>>>(p);
        k_vec_hidden<<<HID, 128>>>(p);
        k_vec_update<<<MEMD + OUTD, 128>>>(p);
    }
    k_vec_gates<1><<<HID, 128>>>(p);

    dim3 g1(HID / TN, BATCH / TM);   // (8, 32)
    k_tgemm<0><<<g1, GEMM_THREADS, SMEM_BYTES>>>(xT, p.W_inp, pre0, IN_DIM, HID, nullptr, nullptr);
    k_tgemm<0><<<g1, GEMM_THREADS, SMEM_BYTES>>>(xT, p.W_ig,  pre1, IN_DIM, HID, nullptr, nullptr);
    k_tgemm<0><<<g1, GEMM_THREADS, SMEM_BYTES>>>(xT, p.W_rg,  pre2, IN_DIM, HID, nullptr, nullptr);

    k_gate_elem<<<(int)(((size_t)BATCH * HID / 4) / 256), 256>>>();

    k_tgemm<1><<<g1, GEMM_THREADS, SMEM_BYTES>>>(rgm, p.W_dec, hid, MEMD, HID, p.b_dec, pre0);

    dim3 g2(OUTD / TN, BATCH / TM);  // (4, 32)
    k_tgemm<0><<<g2, GEMM_THREADS, SMEM_BYTES>>>(hid, p.w_ho, (float*)d_out, MEMD, OUTD, nullptr, nullptr);
}